// round 9
// baseline (speedup 1.0000x reference)
#include <cuda_runtime.h>
#include <math.h>

#define D 64
#define TWOD 128
#define RD 256            // RANK*D
#define W1S 68            // padded stride for W1 rows (== 4 mod 32: conflict-free quarter-warp phases)
#define W2S 132           // padded stride for W2 rows (== 4 mod 32)
#define WARPS 8
#define THREADS 256
#define BROWS 24          // rows per block-iteration (block-cooperative)
#define SLOT 512          // per-row scratch: xv(128, later du/partials) + hs(128, later partials) + wg(256: m->wm->g)

#define SMEM_FLOATS (TWOD*W1S + RD*W2S + TWOD + RD + BROWS*SLOT)

__device__ __forceinline__ float my_tanh(float x) {
    float xc = fminf(fmaxf(x, -10.0f), 10.0f);
    float e = __expf(2.0f * xc);
    return __fdividef(e - 1.0f, e + 1.0f);
}

__global__ __launch_bounds__(THREADS, 1)
void geognn_grad_kernel(const float* __restrict__ input,
                        const float* __restrict__ W1, const float* __restrict__ b1,
                        const float* __restrict__ W2, const float* __restrict__ b2,
                        float* __restrict__ out, int n)
{
    extern __shared__ float smem[];
    float* W1s = smem;                      // [128][68]
    float* W2s = W1s + TWOD * W1S;          // [256][132]
    float* b1s = W2s + RD * W2S;            // [128]
    float* b2s = b1s + TWOD;                // [256]
    float* scr = b2s + RD;                  // BROWS slots of SLOT floats

    const int tid = threadIdx.x;
    const int w   = tid >> 5;
    const int l   = tid & 31;

    // ---- cooperative weight staging ----
    {
        const float4* W1v = (const float4*)W1;
        for (int i = tid; i < TWOD * (D / 4); i += THREADS) {
            int j = i >> 4, k4 = i & 15;
            *(float4*)(W1s + j * W1S + 4 * k4) = W1v[i];
        }
        const float4* W2v = (const float4*)W2;
        for (int i = tid; i < RD * (TWOD / 4); i += THREADS) {
            int j = i >> 5, k4 = i & 31;
            *(float4*)(W2s + j * W2S + 4 * k4) = W2v[i];
        }
        for (int i = tid; i < TWOD; i += THREADS) b1s[i] = b1[i];
        for (int i = tid; i < RD;   i += THREADS) b2s[i] = b2[i];
    }
    __syncthreads();

    const long step = (long)gridDim.x * BROWS;

    for (long base = (long)blockIdx.x * BROWS; base < n; base += step) {
        __syncthreads();   // protect scratch vs previous iteration's readers

        // ==== stage 0: load x|v for 24 rows (warp = one row, coalesced) ====
        for (int idx = tid; idx < BROWS * 32; idx += THREADS) {
            int r = idx >> 5, c = idx & 31;
            int row = (int)base + r; if (row >= n) row = n - 1;
            ((float4*)(scr + r * SLOT))[c] = ((const float4*)(input + (size_t)row * TWOD))[c];
        }
        __syncthreads();

        // ==== stage 1: h = tanh(W1 @ x + b1) — thread owns output j, 12 rows ====
        {
            const int j  = tid & 127;
            const int r0 = (tid >> 7) * 12;
            float acc[12];
            const float bj = b1s[j];
            #pragma unroll
            for (int r = 0; r < 12; r++) acc[r] = bj;
            const float* wrow = W1s + j * W1S;
            #pragma unroll 4
            for (int k = 0; k < D; k += 4) {
                float4 q = *(const float4*)(wrow + k);
                #pragma unroll
                for (int r = 0; r < 12; r++) {
                    float4 xk = *(const float4*)(scr + (r0 + r) * SLOT + k);   // broadcast
                    acc[r] = fmaf(q.x, xk.x, acc[r]); acc[r] = fmaf(q.y, xk.y, acc[r]);
                    acc[r] = fmaf(q.z, xk.z, acc[r]); acc[r] = fmaf(q.w, xk.w, acc[r]);
                }
            }
            #pragma unroll
            for (int r = 0; r < 12; r++)
                scr[(r0 + r) * SLOT + 128 + j] = my_tanh(acc[r]);
        }
        __syncthreads();

        // ==== stage 2: wm = tanh(W2 @ h + b2) — thread owns j and j+128, 12 rows ====
        {
            const int jp = tid & 127;
            const int r0 = (tid >> 7) * 12;
            float acca[12], accb[12];
            const float ba = b2s[jp], bb = b2s[jp + 128];
            #pragma unroll
            for (int r = 0; r < 12; r++) { acca[r] = ba; accb[r] = bb; }
            const float* w2a = W2s + jp * W2S;
            const float* w2b = W2s + (jp + 128) * W2S;
            #pragma unroll 2
            for (int k = 0; k < TWOD; k += 4) {
                float4 qa = *(const float4*)(w2a + k);
                float4 qb = *(const float4*)(w2b + k);
                #pragma unroll
                for (int r = 0; r < 12; r++) {
                    float4 hk = *(const float4*)(scr + (r0 + r) * SLOT + 128 + k);  // broadcast
                    acca[r] = fmaf(qa.x, hk.x, acca[r]); acca[r] = fmaf(qa.y, hk.y, acca[r]);
                    acca[r] = fmaf(qa.z, hk.z, acca[r]); acca[r] = fmaf(qa.w, hk.w, acca[r]);
                    accb[r] = fmaf(qb.x, hk.x, accb[r]); accb[r] = fmaf(qb.y, hk.y, accb[r]);
                    accb[r] = fmaf(qb.z, hk.z, accb[r]); accb[r] = fmaf(qb.w, hk.w, accb[r]);
                }
            }
            #pragma unroll
            for (int r = 0; r < 12; r++) {
                scr[(r0 + r) * SLOT + 256 + jp]       = my_tanh(acca[r]);
                scr[(r0 + r) * SLOT + 256 + jp + 128] = my_tanh(accb[r]);
            }
        }
        __syncthreads();

        // ==== middle: y, g, dv — per-warp, 3 rows per warp (wm register-resident) ====
        {
            #pragma unroll
            for (int rr = 0; rr < 3; rr++) {
                const int r = w * 3 + rr;
                float* sl = scr + r * SLOT;
                float wm[8], vi[8];
                #pragma unroll
                for (int t = 0; t < 8; t++) wm[t] = sl[256 + l + 32 * t];
                #pragma unroll
                for (int t = 0; t < 8; t++) vi[t] = sl[64 + (l >> 2) + 8 * t];

                float y = 0.f;
                #pragma unroll
                for (int t = 0; t < 8; t++) y = fmaf(vi[t], wm[t], y);
                y += __shfl_xor_sync(0xffffffffu, y, 4);
                y += __shfl_xor_sync(0xffffffffu, y, 8);
                y += __shfl_xor_sync(0xffffffffu, y, 16);   // y = y[l&3]

                int row = (int)base + r; if (row >= n) row = n - 1;
                float* outrow = out + (size_t)row * TWOD;
                #pragma unroll
                for (int t = 0; t < 8; t++) {
                    float p = y * wm[t];
                    p += __shfl_xor_sync(0xffffffffu, p, 1);
                    p += __shfl_xor_sync(0xffffffffu, p, 2);
                    if ((l & 3) == 0) outrow[D + (l >> 2) + 8 * t] = -2.0f * p;
                    sl[256 + l + 32 * t] = 2.0f * y * vi[t] * (1.0f - wm[t] * wm[t]);  // g overlays wm
                }
            }
        }
        __syncthreads();

        // ==== stage 3: dh = W2^T @ g ; du = dh*(1-h^2) — split j in halves across warp pairs ====
        {
            const int c  = tid & 31;          // k-chunk 4c..4c+3
            const int jg = (tid >> 5) & 1;    // j-half
            const int rb = (tid >> 6) * 6;    // 6 rows per group
            float4 acc[6];
            #pragma unroll
            for (int r = 0; r < 6; r++) acc[r] = make_float4(0.f, 0.f, 0.f, 0.f);
            const int j0 = jg * 128;
            #pragma unroll 2
            for (int jq = 0; jq < 32; jq++) {
                const int j = j0 + 4 * jq;
                const float* wp = W2s + j * W2S + 4 * c;
                float4 q0 = *(const float4*)(wp);
                float4 q1 = *(const float4*)(wp + W2S);
                float4 q2 = *(const float4*)(wp + 2 * W2S);
                float4 q3 = *(const float4*)(wp + 3 * W2S);
                #pragma unroll
                for (int r = 0; r < 6; r++) {
                    float4 gq = *(const float4*)(scr + (rb + r) * SLOT + 256 + j);   // broadcast
                    acc[r].x = fmaf(gq.x, q0.x, acc[r].x); acc[r].x = fmaf(gq.y, q1.x, acc[r].x);
                    acc[r].x = fmaf(gq.z, q2.x, acc[r].x); acc[r].x = fmaf(gq.w, q3.x, acc[r].x);
                    acc[r].y = fmaf(gq.x, q0.y, acc[r].y); acc[r].y = fmaf(gq.y, q1.y, acc[r].y);
                    acc[r].y = fmaf(gq.z, q2.y, acc[r].y); acc[r].y = fmaf(gq.w, q3.y, acc[r].y);
                    acc[r].z = fmaf(gq.x, q0.z, acc[r].z); acc[r].z = fmaf(gq.y, q1.z, acc[r].z);
                    acc[r].z = fmaf(gq.z, q2.z, acc[r].z); acc[r].z = fmaf(gq.w, q3.z, acc[r].z);
                    acc[r].w = fmaf(gq.x, q0.w, acc[r].w); acc[r].w = fmaf(gq.y, q1.w, acc[r].w);
                    acc[r].w = fmaf(gq.z, q2.w, acc[r].w); acc[r].w = fmaf(gq.w, q3.w, acc[r].w);
                }
            }
            if (jg) {   // write partials into dead x|v region
                #pragma unroll
                for (int r = 0; r < 6; r++)
                    *(float4*)(scr + (rb + r) * SLOT + 4 * c) = acc[r];
            }
            __syncthreads();
            if (!jg) {  // combine, apply (1-h^2), write du in-place
                #pragma unroll
                for (int r = 0; r < 6; r++) {
                    float* px = scr + (rb + r) * SLOT;
                    float4 part = *(const float4*)(px + 4 * c);
                    float4 hk   = *(const float4*)(px + 128 + 4 * c);
                    float4 du;
                    du.x = (acc[r].x + part.x) * (1.0f - hk.x * hk.x);
                    du.y = (acc[r].y + part.y) * (1.0f - hk.y * hk.y);
                    du.z = (acc[r].z + part.z) * (1.0f - hk.z * hk.z);
                    du.w = (acc[r].w + part.w) * (1.0f - hk.w * hk.w);
                    *(float4*)(px + 4 * c) = du;
                }
            }
        }
        __syncthreads();

        // ==== stage 4: dx = W1^T @ du — split j in halves across warp pairs ====
        {
            const int c  = tid & 31;          // i = 2c, 2c+1
            const int jg = (tid >> 5) & 1;
            const int rb = (tid >> 6) * 6;
            float a0[6], a1[6];
            #pragma unroll
            for (int r = 0; r < 6; r++) { a0[r] = 0.f; a1[r] = 0.f; }
            const int j0 = jg * 64;
            #pragma unroll 2
            for (int jq = 0; jq < 16; jq++) {
                const int j = j0 + 4 * jq;
                const float* wp = W1s + j * W1S + 2 * c;
                float2 c0 = *(const float2*)(wp);
                float2 c1 = *(const float2*)(wp + W1S);
                float2 c2 = *(const float2*)(wp + 2 * W1S);
                float2 c3 = *(const float2*)(wp + 3 * W1S);
                #pragma unroll
                for (int r = 0; r < 6; r++) {
                    float4 dq = *(const float4*)(scr + (rb + r) * SLOT + j);   // du broadcast
                    a0[r] = fmaf(dq.x, c0.x, a0[r]); a0[r] = fmaf(dq.y, c1.x, a0[r]);
                    a0[r] = fmaf(dq.z, c2.x, a0[r]); a0[r] = fmaf(dq.w, c3.x, a0[r]);
                    a1[r] = fmaf(dq.x, c0.y, a1[r]); a1[r] = fmaf(dq.y, c1.y, a1[r]);
                    a1[r] = fmaf(dq.z, c2.y, a1[r]); a1[r] = fmaf(dq.w, c3.y, a1[r]);
                }
            }
            if (jg) {   // partials into dead hs region
                #pragma unroll
                for (int r = 0; r < 6; r++)
                    *(float2*)(scr + (rb + r) * SLOT + 128 + 2 * c) = make_float2(a0[r], a1[r]);
            }
            __syncthreads();
            if (!jg) {  // combine + write dx to global
                #pragma unroll
                for (int r = 0; r < 6; r++) {
                    int row = (int)base + rb + r; if (row >= n) row = n - 1;
                    float2 p = *(const float2*)(scr + (rb + r) * SLOT + 128 + 2 * c);
                    *(float2*)(out + (size_t)row * TWOD + 2 * c) =
                        make_float2(a0[r] + p.x, a1[r] + p.y);
                }
            }
        }
    }
}

extern "C" void kernel_launch(void* const* d_in, const int* in_sizes, int n_in,
                              void* d_out, int out_size) {
    // inputs: t(1), input_(N*128), W1(128*64), b1(128), W2(256*128), b2(256)
    const float* input = (const float*)d_in[1];
    const float* W1    = (const float*)d_in[2];
    const float* b1    = (const float*)d_in[3];
    const float* W2    = (const float*)d_in[4];
    const float* b2    = (const float*)d_in[5];
    float* out = (float*)d_out;
    const int n = in_sizes[1] / TWOD;

    static_assert(SMEM_FLOATS * 4 < 232448, "smem budget");

    int dev = 0;
    cudaGetDevice(&dev);
    int nsm = 148;
    cudaDeviceGetAttribute(&nsm, cudaDevAttrMultiProcessorCount, dev);

    cudaFuncSetAttribute(geognn_grad_kernel,
                         cudaFuncAttributeMaxDynamicSharedMemorySize,
                         SMEM_FLOATS * (int)sizeof(float));

    geognn_grad_kernel<<<nsm, THREADS, SMEM_FLOATS * (int)sizeof(float)>>>(
        input, W1, b1, W2, b2, out, n);
}

// round 10
// speedup vs baseline: 1.0046x; 1.0046x over previous
#include <cuda_runtime.h>
#include <math.h>

#define D 64
#define TWOD 128
#define RD 256            // RANK*D
#define W1S 68            // padded stride for W1 rows (== 4 mod 32: conflict-free quarter-warp phases)
#define W2S 132           // padded stride for W2 rows (== 4 mod 32)
#define WARPS 8
#define THREADS 256
#define BROWS 24          // rows per block-iteration (block-cooperative)
#define SLOT 512          // per-row scratch: xv(128, later du/partials) + hs(128, later partials) + wg(256: m->wm->g)

#define SMEM_FLOATS (TWOD*W1S + RD*W2S + TWOD + RD + BROWS*SLOT)

__device__ __forceinline__ float my_tanh(float x) {
    float xc = fminf(fmaxf(x, -10.0f), 10.0f);
    float e = __expf(2.0f * xc);
    return __fdividef(e - 1.0f, e + 1.0f);
}

__global__ __launch_bounds__(THREADS, 1)
void geognn_grad_kernel(const float* __restrict__ input,
                        const float* __restrict__ W1, const float* __restrict__ b1,
                        const float* __restrict__ W2, const float* __restrict__ b2,
                        float* __restrict__ out, int n)
{
    extern __shared__ float smem[];
    float* W1s = smem;                      // [128][68]
    float* W2s = W1s + TWOD * W1S;          // [256][132]
    float* b1s = W2s + RD * W2S;            // [128]
    float* b2s = b1s + TWOD;                // [256]
    float* scr = b2s + RD;                  // BROWS slots of SLOT floats

    const int tid = threadIdx.x;
    const int w   = tid >> 5;
    const int l   = tid & 31;

    // ---- cooperative weight staging ----
    {
        const float4* W1v = (const float4*)W1;
        for (int i = tid; i < TWOD * (D / 4); i += THREADS) {
            int j = i >> 4, k4 = i & 15;
            *(float4*)(W1s + j * W1S + 4 * k4) = W1v[i];
        }
        const float4* W2v = (const float4*)W2;
        for (int i = tid; i < RD * (TWOD / 4); i += THREADS) {
            int j = i >> 5, k4 = i & 31;
            *(float4*)(W2s + j * W2S + 4 * k4) = W2v[i];
        }
        for (int i = tid; i < TWOD; i += THREADS) b1s[i] = b1[i];
        for (int i = tid; i < RD;   i += THREADS) b2s[i] = b2[i];
    }
    __syncthreads();

    const long step = (long)gridDim.x * BROWS;

    for (long base = (long)blockIdx.x * BROWS; base < n; base += step) {
        __syncthreads();   // protect scratch vs previous iteration's readers

        // ==== stage 0: load x|v for 24 rows (warp = one row, coalesced) ====
        for (int idx = tid; idx < BROWS * 32; idx += THREADS) {
            int r = idx >> 5, c = idx & 31;
            int row = (int)base + r; if (row >= n) row = n - 1;
            ((float4*)(scr + r * SLOT))[c] = ((const float4*)(input + (size_t)row * TWOD))[c];
        }
        __syncthreads();

        // ==== stage 1: h = tanh(W1 @ x + b1) — thread owns output j, 12 rows ====
        {
            const int j  = tid & 127;
            const int r0 = (tid >> 7) * 12;
            float acc[12];
            const float bj = b1s[j];
            #pragma unroll
            for (int r = 0; r < 12; r++) acc[r] = bj;
            const float* wrow = W1s + j * W1S;
            #pragma unroll 4
            for (int k = 0; k < D; k += 4) {
                float4 q = *(const float4*)(wrow + k);
                #pragma unroll
                for (int r = 0; r < 12; r++) {
                    float4 xk = *(const float4*)(scr + (r0 + r) * SLOT + k);   // broadcast
                    acc[r] = fmaf(q.x, xk.x, acc[r]); acc[r] = fmaf(q.y, xk.y, acc[r]);
                    acc[r] = fmaf(q.z, xk.z, acc[r]); acc[r] = fmaf(q.w, xk.w, acc[r]);
                }
            }
            #pragma unroll
            for (int r = 0; r < 12; r++)
                scr[(r0 + r) * SLOT + 128 + j] = my_tanh(acc[r]);
        }
        __syncthreads();

        // ==== stage 2: wm = tanh(W2 @ h + b2) — thread owns j and j+128, 12 rows ====
        {
            const int jp = tid & 127;
            const int r0 = (tid >> 7) * 12;
            float acca[12], accb[12];
            const float ba = b2s[jp], bb = b2s[jp + 128];
            #pragma unroll
            for (int r = 0; r < 12; r++) { acca[r] = ba; accb[r] = bb; }
            const float* w2a = W2s + jp * W2S;
            const float* w2b = W2s + (jp + 128) * W2S;
            #pragma unroll 2
            for (int k = 0; k < TWOD; k += 4) {
                float4 qa = *(const float4*)(w2a + k);
                float4 qb = *(const float4*)(w2b + k);
                #pragma unroll
                for (int r = 0; r < 12; r++) {
                    float4 hk = *(const float4*)(scr + (r0 + r) * SLOT + 128 + k);  // broadcast
                    acca[r] = fmaf(qa.x, hk.x, acca[r]); acca[r] = fmaf(qa.y, hk.y, acca[r]);
                    acca[r] = fmaf(qa.z, hk.z, acca[r]); acca[r] = fmaf(qa.w, hk.w, acca[r]);
                    accb[r] = fmaf(qb.x, hk.x, accb[r]); accb[r] = fmaf(qb.y, hk.y, accb[r]);
                    accb[r] = fmaf(qb.z, hk.z, accb[r]); accb[r] = fmaf(qb.w, hk.w, accb[r]);
                }
            }
            #pragma unroll
            for (int r = 0; r < 12; r++) {
                scr[(r0 + r) * SLOT + 256 + jp]       = my_tanh(acca[r]);
                scr[(r0 + r) * SLOT + 256 + jp + 128] = my_tanh(accb[r]);
            }
        }
        __syncthreads();

        // ==== middle: y, g, dv — per-warp, 3 rows per warp (wm register-resident) ====
        {
            #pragma unroll
            for (int rr = 0; rr < 3; rr++) {
                const int r = w * 3 + rr;
                float* sl = scr + r * SLOT;
                float wm[8], vi[8];
                #pragma unroll
                for (int t = 0; t < 8; t++) wm[t] = sl[256 + l + 32 * t];
                #pragma unroll
                for (int t = 0; t < 8; t++) vi[t] = sl[64 + (l >> 2) + 8 * t];

                float y = 0.f;
                #pragma unroll
                for (int t = 0; t < 8; t++) y = fmaf(vi[t], wm[t], y);
                y += __shfl_xor_sync(0xffffffffu, y, 4);
                y += __shfl_xor_sync(0xffffffffu, y, 8);
                y += __shfl_xor_sync(0xffffffffu, y, 16);   // y = y[l&3]

                int row = (int)base + r; if (row >= n) row = n - 1;
                float* outrow = out + (size_t)row * TWOD;
                #pragma unroll
                for (int t = 0; t < 8; t++) {
                    float p = y * wm[t];
                    p += __shfl_xor_sync(0xffffffffu, p, 1);
                    p += __shfl_xor_sync(0xffffffffu, p, 2);
                    if ((l & 3) == 0) outrow[D + (l >> 2) + 8 * t] = -2.0f * p;
                    sl[256 + l + 32 * t] = 2.0f * y * vi[t] * (1.0f - wm[t] * wm[t]);  // g overlays wm
                }
            }
        }
        __syncthreads();

        // ==== stage 3: dh = W2^T @ g ; du = dh*(1-h^2) — split j in halves across warp pairs ====
        {
            const int c  = tid & 31;          // k-chunk 4c..4c+3
            const int jg = (tid >> 5) & 1;    // j-half
            const int rb = (tid >> 6) * 6;    // 6 rows per group
            float4 acc[6];
            #pragma unroll
            for (int r = 0; r < 6; r++) acc[r] = make_float4(0.f, 0.f, 0.f, 0.f);
            const int j0 = jg * 128;
            #pragma unroll 2
            for (int jq = 0; jq < 32; jq++) {
                const int j = j0 + 4 * jq;
                const float* wp = W2s + j * W2S + 4 * c;
                float4 q0 = *(const float4*)(wp);
                float4 q1 = *(const float4*)(wp + W2S);
                float4 q2 = *(const float4*)(wp + 2 * W2S);
                float4 q3 = *(const float4*)(wp + 3 * W2S);
                #pragma unroll
                for (int r = 0; r < 6; r++) {
                    float4 gq = *(const float4*)(scr + (rb + r) * SLOT + 256 + j);   // broadcast
                    acc[r].x = fmaf(gq.x, q0.x, acc[r].x); acc[r].x = fmaf(gq.y, q1.x, acc[r].x);
                    acc[r].x = fmaf(gq.z, q2.x, acc[r].x); acc[r].x = fmaf(gq.w, q3.x, acc[r].x);
                    acc[r].y = fmaf(gq.x, q0.y, acc[r].y); acc[r].y = fmaf(gq.y, q1.y, acc[r].y);
                    acc[r].y = fmaf(gq.z, q2.y, acc[r].y); acc[r].y = fmaf(gq.w, q3.y, acc[r].y);
                    acc[r].z = fmaf(gq.x, q0.z, acc[r].z); acc[r].z = fmaf(gq.y, q1.z, acc[r].z);
                    acc[r].z = fmaf(gq.z, q2.z, acc[r].z); acc[r].z = fmaf(gq.w, q3.z, acc[r].z);
                    acc[r].w = fmaf(gq.x, q0.w, acc[r].w); acc[r].w = fmaf(gq.y, q1.w, acc[r].w);
                    acc[r].w = fmaf(gq.z, q2.w, acc[r].w); acc[r].w = fmaf(gq.w, q3.w, acc[r].w);
                }
            }
            if (jg) {   // write partials into dead x|v region
                #pragma unroll
                for (int r = 0; r < 6; r++)
                    *(float4*)(scr + (rb + r) * SLOT + 4 * c) = acc[r];
            }
            __syncthreads();
            if (!jg) {  // combine, apply (1-h^2), write du in-place
                #pragma unroll
                for (int r = 0; r < 6; r++) {
                    float* px = scr + (rb + r) * SLOT;
                    float4 part = *(const float4*)(px + 4 * c);
                    float4 hk   = *(const float4*)(px + 128 + 4 * c);
                    float4 du;
                    du.x = (acc[r].x + part.x) * (1.0f - hk.x * hk.x);
                    du.y = (acc[r].y + part.y) * (1.0f - hk.y * hk.y);
                    du.z = (acc[r].z + part.z) * (1.0f - hk.z * hk.z);
                    du.w = (acc[r].w + part.w) * (1.0f - hk.w * hk.w);
                    *(float4*)(px + 4 * c) = du;
                }
            }
        }
        __syncthreads();

        // ==== stage 4: dx = W1^T @ du — split j in halves across warp pairs ====
        {
            const int c  = tid & 31;          // i = 2c, 2c+1
            const int jg = (tid >> 5) & 1;
            const int rb = (tid >> 6) * 6;
            float a0[6], a1[6];
            #pragma unroll
            for (int r = 0; r < 6; r++) { a0[r] = 0.f; a1[r] = 0.f; }
            const int j0 = jg * 64;
            #pragma unroll 2
            for (int jq = 0; jq < 16; jq++) {
                const int j = j0 + 4 * jq;
                const float* wp = W1s + j * W1S + 2 * c;
                float2 c0 = *(const float2*)(wp);
                float2 c1 = *(const float2*)(wp + W1S);
                float2 c2 = *(const float2*)(wp + 2 * W1S);
                float2 c3 = *(const float2*)(wp + 3 * W1S);
                #pragma unroll
                for (int r = 0; r < 6; r++) {
                    float4 dq = *(const float4*)(scr + (rb + r) * SLOT + j);   // du broadcast
                    a0[r] = fmaf(dq.x, c0.x, a0[r]); a0[r] = fmaf(dq.y, c1.x, a0[r]);
                    a0[r] = fmaf(dq.z, c2.x, a0[r]); a0[r] = fmaf(dq.w, c3.x, a0[r]);
                    a1[r] = fmaf(dq.x, c0.y, a1[r]); a1[r] = fmaf(dq.y, c1.y, a1[r]);
                    a1[r] = fmaf(dq.z, c2.y, a1[r]); a1[r] = fmaf(dq.w, c3.y, a1[r]);
                }
            }
            if (jg) {   // partials into dead hs region
                #pragma unroll
                for (int r = 0; r < 6; r++)
                    *(float2*)(scr + (rb + r) * SLOT + 128 + 2 * c) = make_float2(a0[r], a1[r]);
            }
            __syncthreads();
            if (!jg) {  // combine + write dx to global
                #pragma unroll
                for (int r = 0; r < 6; r++) {
                    int row = (int)base + rb + r; if (row >= n) row = n - 1;
                    float2 p = *(const float2*)(scr + (rb + r) * SLOT + 128 + 2 * c);
                    *(float2*)(out + (size_t)row * TWOD + 2 * c) =
                        make_float2(a0[r] + p.x, a1[r] + p.y);
                }
            }
        }
    }
}

extern "C" void kernel_launch(void* const* d_in, const int* in_sizes, int n_in,
                              void* d_out, int out_size) {
    // inputs: t(1), input_(N*128), W1(128*64), b1(128), W2(256*128), b2(256)
    const float* input = (const float*)d_in[1];
    const float* W1    = (const float*)d_in[2];
    const float* b1    = (const float*)d_in[3];
    const float* W2    = (const float*)d_in[4];
    const float* b2    = (const float*)d_in[5];
    float* out = (float*)d_out;
    const int n = in_sizes[1] / TWOD;

    static_assert(SMEM_FLOATS * 4 < 232448, "smem budget");

    int dev = 0;
    cudaGetDevice(&dev);
    int nsm = 148;
    cudaDeviceGetAttribute(&nsm, cudaDevAttrMultiProcessorCount, dev);

    cudaFuncSetAttribute(geognn_grad_kernel,
                         cudaFuncAttributeMaxDynamicSharedMemorySize,
                         SMEM_FLOATS * (int)sizeof(float));

    geognn_grad_kernel<<<nsm, THREADS, SMEM_FLOATS * (int)sizeof(float)>>>(
        input, W1, b1, W2, b2, out, n);
}

// round 11
// speedup vs baseline: 1.0876x; 1.0826x over previous
#include <cuda_runtime.h>
#include <math.h>

#define D 64
#define TWOD 128
#define RD 256            // RANK*D
#define W1S 68            // padded stride for W1 rows (conflict-free both ways)
#define WARPS 10
#define THREADS 320
#define RB 4              // rows per warp
#define SLOT 384          // per-row scratch: A[128]=x|v->g_lo->du, B[128]=h, C[128]=g_hi

// W2 stored stride-128 with XOR chunk swizzle (no padding needed)
#define SMEM_FLOATS (TWOD*W1S + RD*TWOD + TWOD + RD + WARPS*RB*SLOT)

__device__ __forceinline__ float my_tanh(float x) {
    float xc = fminf(fmaxf(x, -10.0f), 10.0f);
    float e = __expf(2.0f * xc);
    return __fdividef(e - 1.0f, e + 1.0f);
}

__global__ __launch_bounds__(THREADS, 1)
void geognn_grad_kernel(const float* __restrict__ input,
                        const float* __restrict__ W1, const float* __restrict__ b1,
                        const float* __restrict__ W2, const float* __restrict__ b2,
                        float* __restrict__ out, int n)
{
    extern __shared__ float smem[];
    float* W1s = smem;                 // [128][68]
    float* W2s = W1s + TWOD * W1S;     // [256][128], chunk k4 stored at k4^(j&31)
    float* b1s = W2s + RD * TWOD;      // [128]
    float* b2s = b1s + TWOD;           // [256]
    float* scr = b2s + RD;             // WARPS*RB slots of SLOT floats

    const int tid = threadIdx.x;
    const int w   = tid >> 5;
    const int l   = tid & 31;

    // ---- cooperative weight staging ----
    {
        const float4* W1v = (const float4*)W1;
        for (int i = tid; i < TWOD * (D / 4); i += THREADS) {
            int j = i >> 4, k4 = i & 15;
            *(float4*)(W1s + j * W1S + 4 * k4) = W1v[i];
        }
        const float4* W2v = (const float4*)W2;
        for (int i = tid; i < RD * (TWOD / 4); i += THREADS) {
            int j = i >> 5, k4 = i & 31;
            *(float4*)(W2s + j * TWOD + 4 * (k4 ^ (j & 31))) = W2v[i];
        }
        for (int i = tid; i < TWOD; i += THREADS) b1s[i] = b1[i];
        for (int i = tid; i < RD;   i += THREADS) b2s[i] = b2[i];
    }
    __syncthreads();

    float* slot[RB];
    #pragma unroll
    for (int r = 0; r < RB; r++) slot[r] = scr + (w * RB + r) * SLOT;

    const int gw = blockIdx.x * WARPS + w;
    const long stride = (long)gridDim.x * WARPS * RB;

    for (long base = (long)gw * RB; base < n; base += stride) {
        __syncwarp();   // protect scratch reuse across iterations

        int rows[RB];
        #pragma unroll
        for (int r = 0; r < RB; r++) {
            long rr = base + r;
            rows[r] = (rr < n) ? (int)rr : (n - 1);  // clamp: duplicate work, identical stores
        }

        // ---- load x|v into A ----
        #pragma unroll
        for (int r = 0; r < RB; r++)
            ((float4*)slot[r])[l] = ((const float4*)(input + (size_t)rows[r] * TWOD))[l];
        __syncwarp();

        // ==== fwd1: h = tanh(W1 @ x + b1), lane owns j = l+32p ====
        {
            float a[RB][4];
            #pragma unroll
            for (int r = 0; r < RB; r++)
                #pragma unroll
                for (int p = 0; p < 4; p++) a[r][p] = b1s[l + 32 * p];

            const float* p0 = W1s + (l)      * W1S;
            const float* p1 = W1s + (l + 32) * W1S;
            const float* p2 = W1s + (l + 64) * W1S;
            const float* p3 = W1s + (l + 96) * W1S;
            #pragma unroll 4
            for (int k = 0; k < D; k += 4) {
                float4 q0 = *(const float4*)(p0 + k);
                float4 q1 = *(const float4*)(p1 + k);
                float4 q2 = *(const float4*)(p2 + k);
                float4 q3 = *(const float4*)(p3 + k);
                #pragma unroll
                for (int r = 0; r < RB; r++) {
                    float4 xk = *(const float4*)(slot[r] + k);   // broadcast
                    a[r][0] = fmaf(q0.x, xk.x, a[r][0]); a[r][0] = fmaf(q0.y, xk.y, a[r][0]);
                    a[r][0] = fmaf(q0.z, xk.z, a[r][0]); a[r][0] = fmaf(q0.w, xk.w, a[r][0]);
                    a[r][1] = fmaf(q1.x, xk.x, a[r][1]); a[r][1] = fmaf(q1.y, xk.y, a[r][1]);
                    a[r][1] = fmaf(q1.z, xk.z, a[r][1]); a[r][1] = fmaf(q1.w, xk.w, a[r][1]);
                    a[r][2] = fmaf(q2.x, xk.x, a[r][2]); a[r][2] = fmaf(q2.y, xk.y, a[r][2]);
                    a[r][2] = fmaf(q2.z, xk.z, a[r][2]); a[r][2] = fmaf(q2.w, xk.w, a[r][2]);
                    a[r][3] = fmaf(q3.x, xk.x, a[r][3]); a[r][3] = fmaf(q3.y, xk.y, a[r][3]);
                    a[r][3] = fmaf(q3.z, xk.z, a[r][3]); a[r][3] = fmaf(q3.w, xk.w, a[r][3]);
                }
            }
            #pragma unroll
            for (int r = 0; r < RB; r++) {
                slot[r][128 + l]      = my_tanh(a[r][0]);
                slot[r][128 + l + 32] = my_tanh(a[r][1]);
                slot[r][128 + l + 64] = my_tanh(a[r][2]);
                slot[r][128 + l + 96] = my_tanh(a[r][3]);
            }
        }
        __syncwarp();

        // ==== fwd2: m = W2 @ h + b2, lane owns j = l+32t (t=0..7) ====
        float mac[8][RB];
        #pragma unroll
        for (int t = 0; t < 8; t++)
            #pragma unroll
            for (int r = 0; r < RB; r++) mac[t][r] = b2s[l + 32 * t];

        #pragma unroll 2
        for (int k4 = 0; k4 < 32; k4++) {
            const int koff = 4 * (k4 ^ l);       // swizzled chunk for row-group l
            float4 hk[RB];
            #pragma unroll
            for (int r = 0; r < RB; r++) hk[r] = *(const float4*)(slot[r] + 128 + 4 * k4);
            #pragma unroll
            for (int t = 0; t < 8; t++) {
                float4 q = *(const float4*)(W2s + (l + 32 * t) * TWOD + koff);
                #pragma unroll
                for (int r = 0; r < RB; r++) {
                    mac[t][r] = fmaf(q.x, hk[r].x, mac[t][r]);
                    mac[t][r] = fmaf(q.y, hk[r].y, mac[t][r]);
                    mac[t][r] = fmaf(q.z, hk[r].z, mac[t][r]);
                    mac[t][r] = fmaf(q.w, hk[r].w, mac[t][r]);
                }
            }
        }

        // ==== middle: wm (regs), y, dv, g — per row ====
        #pragma unroll
        for (int r = 0; r < RB; r++) {
            float wm[8], vi[8];
            #pragma unroll
            for (int t = 0; t < 8; t++) wm[t] = my_tanh(mac[t][r]);
            #pragma unroll
            for (int t = 0; t < 8; t++) vi[t] = slot[r][64 + (l >> 2) + 8 * t];

            float y = 0.f;
            #pragma unroll
            for (int t = 0; t < 8; t++) y = fmaf(vi[t], wm[t], y);
            y += __shfl_xor_sync(0xffffffffu, y, 4);
            y += __shfl_xor_sync(0xffffffffu, y, 8);
            y += __shfl_xor_sync(0xffffffffu, y, 16);   // y = y[l&3] on all lanes

            float* outrow = out + (size_t)rows[r] * TWOD;
            #pragma unroll
            for (int t = 0; t < 8; t++) {
                float p = y * wm[t];
                p += __shfl_xor_sync(0xffffffffu, p, 1);
                p += __shfl_xor_sync(0xffffffffu, p, 2);
                if ((l & 3) == 0) outrow[D + (l >> 2) + 8 * t] = -2.0f * p;
                float g = 2.0f * y * vi[t] * (1.0f - wm[t] * wm[t]);
                if (t < 4) slot[r][l + 32 * t]            = g;   // g_lo over dead x|v
                else       slot[r][256 + l + 32 * t - 128] = g;  // g_hi in C
            }
        }
        __syncwarp();

        // ==== bwd W2: dh[k] = sum_j W2[j][k]*g[j]; lane owns k = 4l..4l+3 ====
        {
            float4 dacc[RB];
            #pragma unroll
            for (int r = 0; r < RB; r++) dacc[r] = make_float4(0.f, 0.f, 0.f, 0.f);

            #pragma unroll 2
            for (int jq = 0; jq < 64; jq++) {
                const int j  = 4 * jq;
                const int jb = j & 31;
                const float* wp = W2s + j * TWOD;
                float4 q0 = *(const float4*)(wp            + 4 * (l ^ (jb)));
                float4 q1 = *(const float4*)(wp + TWOD     + 4 * (l ^ (jb + 1)));
                float4 q2 = *(const float4*)(wp + 2 * TWOD + 4 * (l ^ (jb + 2)));
                float4 q3 = *(const float4*)(wp + 3 * TWOD + 4 * (l ^ (jb + 3)));
                const int goff = (jq < 32) ? j : (256 + j - 128);   // A then C
                #pragma unroll
                for (int r = 0; r < RB; r++) {
                    float4 gq = *(const float4*)(slot[r] + goff);   // broadcast
                    dacc[r].x = fmaf(gq.x, q0.x, dacc[r].x); dacc[r].x = fmaf(gq.y, q1.x, dacc[r].x);
                    dacc[r].x = fmaf(gq.z, q2.x, dacc[r].x); dacc[r].x = fmaf(gq.w, q3.x, dacc[r].x);
                    dacc[r].y = fmaf(gq.x, q0.y, dacc[r].y); dacc[r].y = fmaf(gq.y, q1.y, dacc[r].y);
                    dacc[r].y = fmaf(gq.z, q2.y, dacc[r].y); dacc[r].y = fmaf(gq.w, q3.y, dacc[r].y);
                    dacc[r].z = fmaf(gq.x, q0.z, dacc[r].z); dacc[r].z = fmaf(gq.y, q1.z, dacc[r].z);
                    dacc[r].z = fmaf(gq.z, q2.z, dacc[r].z); dacc[r].z = fmaf(gq.w, q3.z, dacc[r].z);
                    dacc[r].w = fmaf(gq.x, q0.w, dacc[r].w); dacc[r].w = fmaf(gq.y, q1.w, dacc[r].w);
                    dacc[r].w = fmaf(gq.z, q2.w, dacc[r].w); dacc[r].w = fmaf(gq.w, q3.w, dacc[r].w);
                }
            }
            __syncwarp();   // all g reads done before du overwrites A
            #pragma unroll
            for (int r = 0; r < RB; r++) {
                float4 hk = *(const float4*)(slot[r] + 128 + 4 * l);
                float4 du;
                du.x = dacc[r].x * (1.0f - hk.x * hk.x);
                du.y = dacc[r].y * (1.0f - hk.y * hk.y);
                du.z = dacc[r].z * (1.0f - hk.z * hk.z);
                du.w = dacc[r].w * (1.0f - hk.w * hk.w);
                *(float4*)(slot[r] + 4 * l) = du;     // du over g_lo
            }
        }
        __syncwarp();

        // ==== bwd W1: dx[i] = sum_j W1[j][i]*du[j]; lane owns i = 2l, 2l+1 ====
        {
            float xo[RB][2];
            #pragma unroll
            for (int r = 0; r < RB; r++) { xo[r][0] = 0.f; xo[r][1] = 0.f; }
            const float* c1 = W1s + 2 * l;
            #pragma unroll 2
            for (int jq = 0; jq < 32; jq++) {
                const int j = 4 * jq;
                float2 c0 = *(const float2*)(c1 + (j)     * W1S);
                float2 ca = *(const float2*)(c1 + (j + 1) * W1S);
                float2 cb = *(const float2*)(c1 + (j + 2) * W1S);
                float2 cc = *(const float2*)(c1 + (j + 3) * W1S);
                #pragma unroll
                for (int r = 0; r < RB; r++) {
                    float4 dq = *(const float4*)(slot[r] + j);   // du broadcast
                    xo[r][0] = fmaf(dq.x, c0.x, xo[r][0]); xo[r][0] = fmaf(dq.y, ca.x, xo[r][0]);
                    xo[r][0] = fmaf(dq.z, cb.x, xo[r][0]); xo[r][0] = fmaf(dq.w, cc.x, xo[r][0]);
                    xo[r][1] = fmaf(dq.x, c0.y, xo[r][1]); xo[r][1] = fmaf(dq.y, ca.y, xo[r][1]);
                    xo[r][1] = fmaf(dq.z, cb.y, xo[r][1]); xo[r][1] = fmaf(dq.w, cc.y, xo[r][1]);
                }
            }
            #pragma unroll
            for (int r = 0; r < RB; r++)
                *(float2*)(out + (size_t)rows[r] * TWOD + 2 * l) = make_float2(xo[r][0], xo[r][1]);
        }
    }
}

extern "C" void kernel_launch(void* const* d_in, const int* in_sizes, int n_in,
                              void* d_out, int out_size) {
    // inputs: t(1), input_(N*128), W1(128*64), b1(128), W2(256*128), b2(256)
    const float* input = (const float*)d_in[1];
    const float* W1    = (const float*)d_in[2];
    const float* b1    = (const float*)d_in[3];
    const float* W2    = (const float*)d_in[4];
    const float* b2    = (const float*)d_in[5];
    float* out = (float*)d_out;
    const int n = in_sizes[1] / TWOD;

    static_assert(SMEM_FLOATS * 4 < 232448, "smem budget");

    int dev = 0;
    cudaGetDevice(&dev);
    int nsm = 148;
    cudaDeviceGetAttribute(&nsm, cudaDevAttrMultiProcessorCount, dev);

    cudaFuncSetAttribute(geognn_grad_kernel,
                         cudaFuncAttributeMaxDynamicSharedMemorySize,
                         SMEM_FLOATS * (int)sizeof(float));

    geognn_grad_kernel<<<nsm, THREADS, SMEM_FLOATS * (int)sizeof(float)>>>(
        input, W1, b1, W2, b2, out, n);
}

// round 12
// speedup vs baseline: 1.1152x; 1.0254x over previous
#include <cuda_runtime.h>
#include <math.h>

#define D 64
#define TWOD 128
#define RD 256            // RANK*D
#define W1S 68            // padded stride for W1 rows (conflict-free LDS.128 both ways)
#define WARPS 10
#define THREADS 320
#define RB 4              // rows per warp
#define SLOT 384          // per-row scratch: A[128]=x|v->g_lo->du, B[128]=h, C[128]=g_hi

// W2 stored stride-128 with XOR chunk swizzle
#define SMEM_FLOATS (TWOD*W1S + RD*TWOD + TWOD + RD + WARPS*RB*SLOT)

typedef unsigned long long ull;

__device__ __forceinline__ ull pack2(float lo, float hi) {
    ull r; asm("mov.b64 %0, {%1, %2};" : "=l"(r) : "f"(lo), "f"(hi)); return r;
}
__device__ __forceinline__ float2 unpack2(ull v) {
    float2 f; asm("mov.b64 {%0, %1}, %2;" : "=f"(f.x), "=f"(f.y) : "l"(v)); return f;
}
__device__ __forceinline__ ull ffma2(ull a, ull b, ull c) {
    ull d; asm("fma.rn.f32x2 %0, %1, %2, %3;" : "=l"(d) : "l"(a), "l"(b), "l"(c)); return d;
}
__device__ __forceinline__ float hadd2(ull v) { float2 f = unpack2(v); return f.x + f.y; }

__device__ __forceinline__ float my_tanh(float x) {
    float xc = fminf(fmaxf(x, -10.0f), 10.0f);
    float e = __expf(2.0f * xc);
    return __fdividef(e - 1.0f, e + 1.0f);
}

__global__ __launch_bounds__(THREADS, 1)
void geognn_grad_kernel(const float* __restrict__ input,
                        const float* __restrict__ W1, const float* __restrict__ b1,
                        const float* __restrict__ W2, const float* __restrict__ b2,
                        float* __restrict__ out, int n)
{
    extern __shared__ float smem[];
    float* W1s = smem;                 // [128][68]
    float* W2s = W1s + TWOD * W1S;     // [256][128], chunk k4 stored at k4^(j&31)
    float* b1s = W2s + RD * TWOD;      // [128]
    float* b2s = b1s + TWOD;           // [256]
    float* scr = b2s + RD;

    const int tid = threadIdx.x;
    const int w   = tid >> 5;
    const int l   = tid & 31;

    // ---- cooperative weight staging ----
    {
        const float4* W1v = (const float4*)W1;
        for (int i = tid; i < TWOD * (D / 4); i += THREADS) {
            int j = i >> 4, k4 = i & 15;
            *(float4*)(W1s + j * W1S + 4 * k4) = W1v[i];
        }
        const float4* W2v = (const float4*)W2;
        for (int i = tid; i < RD * (TWOD / 4); i += THREADS) {
            int j = i >> 5, k4 = i & 31;
            *(float4*)(W2s + j * TWOD + 4 * (k4 ^ (j & 31))) = W2v[i];
        }
        for (int i = tid; i < TWOD; i += THREADS) b1s[i] = b1[i];
        for (int i = tid; i < RD;   i += THREADS) b2s[i] = b2[i];
    }
    __syncthreads();

    float* slot[RB];
    #pragma unroll
    for (int r = 0; r < RB; r++) slot[r] = scr + (w * RB + r) * SLOT;

    const int gw = blockIdx.x * WARPS + w;
    const long stride = (long)gridDim.x * WARPS * RB;

    for (long base = (long)gw * RB; base < n; base += stride) {
        __syncwarp();

        int rows[RB];
        #pragma unroll
        for (int r = 0; r < RB; r++) {
            long rr = base + r;
            rows[r] = (rr < n) ? (int)rr : (n - 1);
        }

        // ---- load x|v into A ----
        #pragma unroll
        for (int r = 0; r < RB; r++)
            ((float4*)slot[r])[l] = ((const float4*)(input + (size_t)rows[r] * TWOD))[l];
        __syncwarp();

        // ==== fwd1: h = tanh(W1 @ x + b1), lane owns j = l+32p — packed over k ====
        {
            ull a2[RB][4];
            #pragma unroll
            for (int r = 0; r < RB; r++)
                #pragma unroll
                for (int p = 0; p < 4; p++) a2[r][p] = pack2(b1s[l + 32 * p], 0.0f);

            const float* p0 = W1s + (l)      * W1S;
            const float* p1 = W1s + (l + 32) * W1S;
            const float* p2 = W1s + (l + 64) * W1S;
            const float* p3 = W1s + (l + 96) * W1S;
            #pragma unroll 4
            for (int k = 0; k < D; k += 4) {
                ulonglong2 q0 = *(const ulonglong2*)(p0 + k);
                ulonglong2 q1 = *(const ulonglong2*)(p1 + k);
                ulonglong2 q2 = *(const ulonglong2*)(p2 + k);
                ulonglong2 q3 = *(const ulonglong2*)(p3 + k);
                #pragma unroll
                for (int r = 0; r < RB; r++) {
                    ulonglong2 xk = *(const ulonglong2*)(slot[r] + k);   // broadcast
                    a2[r][0] = ffma2(q0.x, xk.x, a2[r][0]); a2[r][0] = ffma2(q0.y, xk.y, a2[r][0]);
                    a2[r][1] = ffma2(q1.x, xk.x, a2[r][1]); a2[r][1] = ffma2(q1.y, xk.y, a2[r][1]);
                    a2[r][2] = ffma2(q2.x, xk.x, a2[r][2]); a2[r][2] = ffma2(q2.y, xk.y, a2[r][2]);
                    a2[r][3] = ffma2(q3.x, xk.x, a2[r][3]); a2[r][3] = ffma2(q3.y, xk.y, a2[r][3]);
                }
            }
            #pragma unroll
            for (int r = 0; r < RB; r++) {
                slot[r][128 + l]      = my_tanh(hadd2(a2[r][0]));
                slot[r][128 + l + 32] = my_tanh(hadd2(a2[r][1]));
                slot[r][128 + l + 64] = my_tanh(hadd2(a2[r][2]));
                slot[r][128 + l + 96] = my_tanh(hadd2(a2[r][3]));
            }
        }
        __syncwarp();

        // ==== fwd2: m = W2 @ h + b2, lane owns j = l+32t — packed over k ====
        ull mac2[8][RB];
        #pragma unroll
        for (int t = 0; t < 8; t++)
            #pragma unroll
            for (int r = 0; r < RB; r++) mac2[t][r] = pack2(b2s[l + 32 * t], 0.0f);

        #pragma unroll 2
        for (int k4 = 0; k4 < 32; k4++) {
            const int koff = 4 * (k4 ^ l);
            ulonglong2 hk2[RB];
            #pragma unroll
            for (int r = 0; r < RB; r++) hk2[r] = *(const ulonglong2*)(slot[r] + 128 + 4 * k4);
            #pragma unroll
            for (int t = 0; t < 8; t++) {
                ulonglong2 q = *(const ulonglong2*)(W2s + (l + 32 * t) * TWOD + koff);
                #pragma unroll
                for (int r = 0; r < RB; r++) {
                    mac2[t][r] = ffma2(q.x, hk2[r].x, mac2[t][r]);
                    mac2[t][r] = ffma2(q.y, hk2[r].y, mac2[t][r]);
                }
            }
        }

        // ==== middle: wm (regs), y, dv, g — per row ====
        #pragma unroll
        for (int r = 0; r < RB; r++) {
            float wm[8], vi[8];
            #pragma unroll
            for (int t = 0; t < 8; t++) wm[t] = my_tanh(hadd2(mac2[t][r]));
            #pragma unroll
            for (int t = 0; t < 8; t++) vi[t] = slot[r][64 + (l >> 2) + 8 * t];

            float y = 0.f;
            #pragma unroll
            for (int t = 0; t < 8; t++) y = fmaf(vi[t], wm[t], y);
            y += __shfl_xor_sync(0xffffffffu, y, 4);
            y += __shfl_xor_sync(0xffffffffu, y, 8);
            y += __shfl_xor_sync(0xffffffffu, y, 16);   // y = y[l&3] on all lanes

            float* outrow = out + (size_t)rows[r] * TWOD;
            #pragma unroll
            for (int t = 0; t < 8; t++) {
                float p = y * wm[t];
                p += __shfl_xor_sync(0xffffffffu, p, 1);
                p += __shfl_xor_sync(0xffffffffu, p, 2);
                if ((l & 3) == 0) outrow[D + (l >> 2) + 8 * t] = -2.0f * p;
                float g = 2.0f * y * vi[t] * (1.0f - wm[t] * wm[t]);
                if (t < 4) slot[r][l + 32 * t]             = g;   // g_lo over dead x|v
                else       slot[r][256 + l + 32 * t - 128] = g;   // g_hi in C
            }
        }
        __syncwarp();

        // ==== bwd W2: dh[k] = sum_j W2[j][k]*g[j]; lane owns k = 4l..4l+3 — packed over k ====
        {
            ull dacc2[RB][2];
            #pragma unroll
            for (int r = 0; r < RB; r++) { dacc2[r][0] = 0ull; dacc2[r][1] = 0ull; }

            #pragma unroll 2
            for (int jq = 0; jq < 64; jq++) {
                const int j  = 4 * jq;
                const int jb = j & 31;
                const float* wp = W2s + j * TWOD;
                ulonglong2 q0 = *(const ulonglong2*)(wp            + 4 * (l ^ (jb)));
                ulonglong2 q1 = *(const ulonglong2*)(wp + TWOD     + 4 * (l ^ (jb + 1)));
                ulonglong2 q2 = *(const ulonglong2*)(wp + 2 * TWOD + 4 * (l ^ (jb + 2)));
                ulonglong2 q3 = *(const ulonglong2*)(wp + 3 * TWOD + 4 * (l ^ (jb + 3)));
                const int goff = (jq < 32) ? j : (256 + j - 128);
                #pragma unroll
                for (int r = 0; r < RB; r++) {
                    float4 gq = *(const float4*)(slot[r] + goff);    // broadcast
                    ull gx = pack2(gq.x, gq.x), gy = pack2(gq.y, gq.y);
                    ull gz = pack2(gq.z, gq.z), gw = pack2(gq.w, gq.w);
                    dacc2[r][0] = ffma2(gx, q0.x, dacc2[r][0]);
                    dacc2[r][0] = ffma2(gy, q1.x, dacc2[r][0]);
                    dacc2[r][0] = ffma2(gz, q2.x, dacc2[r][0]);
                    dacc2[r][0] = ffma2(gw, q3.x, dacc2[r][0]);
                    dacc2[r][1] = ffma2(gx, q0.y, dacc2[r][1]);
                    dacc2[r][1] = ffma2(gy, q1.y, dacc2[r][1]);
                    dacc2[r][1] = ffma2(gz, q2.y, dacc2[r][1]);
                    dacc2[r][1] = ffma2(gw, q3.y, dacc2[r][1]);
                }
            }
            __syncwarp();   // all g reads done before du overwrites A
            #pragma unroll
            for (int r = 0; r < RB; r++) {
                float2 dA = unpack2(dacc2[r][0]);
                float2 dB = unpack2(dacc2[r][1]);
                float4 hk = *(const float4*)(slot[r] + 128 + 4 * l);
                float4 du;
                du.x = dA.x * (1.0f - hk.x * hk.x);
                du.y = dA.y * (1.0f - hk.y * hk.y);
                du.z = dB.x * (1.0f - hk.z * hk.z);
                du.w = dB.y * (1.0f - hk.w * hk.w);
                *(float4*)(slot[r] + 4 * l) = du;     // du over g_lo
            }
        }
        __syncwarp();

        // ==== bwd W1: dx[i] = sum_j W1[j][i]*du[j]; lane owns i = 2l,2l+1 — packed over i ====
        {
            ull xo2[RB];
            #pragma unroll
            for (int r = 0; r < RB; r++) xo2[r] = 0ull;
            const float* c1 = W1s + 2 * l;
            #pragma unroll 2
            for (int jq = 0; jq < 32; jq++) {
                const int j = 4 * jq;
                ull c0 = *(const ull*)(c1 + (j)     * W1S);
                ull ca = *(const ull*)(c1 + (j + 1) * W1S);
                ull cb = *(const ull*)(c1 + (j + 2) * W1S);
                ull cc = *(const ull*)(c1 + (j + 3) * W1S);
                #pragma unroll
                for (int r = 0; r < RB; r++) {
                    float4 dq = *(const float4*)(slot[r] + j);   // du broadcast
                    xo2[r] = ffma2(pack2(dq.x, dq.x), c0, xo2[r]);
                    xo2[r] = ffma2(pack2(dq.y, dq.y), ca, xo2[r]);
                    xo2[r] = ffma2(pack2(dq.z, dq.z), cb, xo2[r]);
                    xo2[r] = ffma2(pack2(dq.w, dq.w), cc, xo2[r]);
                }
            }
            #pragma unroll
            for (int r = 0; r < RB; r++) {
                float2 xr = unpack2(xo2[r]);
                *(float2*)(out + (size_t)rows[r] * TWOD + 2 * l) = xr;
            }
        }
    }
}

extern "C" void kernel_launch(void* const* d_in, const int* in_sizes, int n_in,
                              void* d_out, int out_size) {
    // inputs: t(1), input_(N*128), W1(128*64), b1(128), W2(256*128), b2(256)
    const float* input = (const float*)d_in[1];
    const float* W1    = (const float*)d_in[2];
    const float* b1    = (const float*)d_in[3];
    const float* W2    = (const float*)d_in[4];
    const float* b2    = (const float*)d_in[5];
    float* out = (float*)d_out;
    const int n = in_sizes[1] / TWOD;

    static_assert(SMEM_FLOATS * 4 < 232448, "smem budget");

    int dev = 0;
    cudaGetDevice(&dev);
    int nsm = 148;
    cudaDeviceGetAttribute(&nsm, cudaDevAttrMultiProcessorCount, dev);

    cudaFuncSetAttribute(geognn_grad_kernel,
                         cudaFuncAttributeMaxDynamicSharedMemorySize,
                         SMEM_FLOATS * (int)sizeof(float));

    geognn_grad_kernel<<<nsm, THREADS, SMEM_FLOATS * (int)sizeof(float)>>>(
        input, W1, b1, W2, b2, out, n);
}

// round 13
// speedup vs baseline: 1.2802x; 1.1479x over previous
#include <cuda_runtime.h>
#include <math.h>

#define D 64
#define TWOD 128
#define RD 256            // RANK*D
#define W1S 68            // padded stride for W1 rows (conflict-free LDS.128 both ways)
#define WARPS 8
#define THREADS 256
#define RB 5              // rows per warp
#define SLOT 384          // per-row scratch: A[128]=x|v->g_lo->du, B[128]=h, C[128]=g_hi

// W2 stored stride-128 with XOR chunk swizzle
#define SMEM_FLOATS (TWOD*W1S + RD*TWOD + TWOD + RD + WARPS*RB*SLOT)

typedef unsigned long long ull;

__device__ __forceinline__ ull pack2(float lo, float hi) {
    ull r; asm("mov.b64 %0, {%1, %2};" : "=l"(r) : "f"(lo), "f"(hi)); return r;
}
__device__ __forceinline__ float2 unpack2(ull v) {
    float2 f; asm("mov.b64 {%0, %1}, %2;" : "=f"(f.x), "=f"(f.y) : "l"(v)); return f;
}
__device__ __forceinline__ ull ffma2(ull a, ull b, ull c) {
    ull d; asm("fma.rn.f32x2 %0, %1, %2, %3;" : "=l"(d) : "l"(a), "l"(b), "l"(c)); return d;
}
__device__ __forceinline__ float hadd2(ull v) { float2 f = unpack2(v); return f.x + f.y; }

__device__ __forceinline__ float my_tanh(float x) {
    float xc = fminf(fmaxf(x, -10.0f), 10.0f);
    float e = __expf(2.0f * xc);
    return __fdividef(e - 1.0f, e + 1.0f);
}

__global__ __launch_bounds__(THREADS, 1)
void geognn_grad_kernel(const float* __restrict__ input,
                        const float* __restrict__ W1, const float* __restrict__ b1,
                        const float* __restrict__ W2, const float* __restrict__ b2,
                        float* __restrict__ out, int n)
{
    extern __shared__ float smem[];
    float* W1s = smem;                 // [128][68]
    float* W2s = W1s + TWOD * W1S;     // [256][128], chunk k4 stored at k4^(j&31)
    float* b1s = W2s + RD * TWOD;      // [128]
    float* b2s = b1s + TWOD;           // [256]
    float* scr = b2s + RD;

    const int tid = threadIdx.x;
    const int w   = tid >> 5;
    const int l   = tid & 31;

    // ---- cooperative weight staging ----
    {
        const float4* W1v = (const float4*)W1;
        for (int i = tid; i < TWOD * (D / 4); i += THREADS) {
            int j = i >> 4, k4 = i & 15;
            *(float4*)(W1s + j * W1S + 4 * k4) = W1v[i];
        }
        const float4* W2v = (const float4*)W2;
        for (int i = tid; i < RD * (TWOD / 4); i += THREADS) {
            int j = i >> 5, k4 = i & 31;
            *(float4*)(W2s + j * TWOD + 4 * (k4 ^ (j & 31))) = W2v[i];
        }
        for (int i = tid; i < TWOD; i += THREADS) b1s[i] = b1[i];
        for (int i = tid; i < RD;   i += THREADS) b2s[i] = b2[i];
    }
    __syncthreads();

    float* slot[RB];
    #pragma unroll
    for (int r = 0; r < RB; r++) slot[r] = scr + (w * RB + r) * SLOT;

    const int gw = blockIdx.x * WARPS + w;
    const long stride = (long)gridDim.x * WARPS * RB;

    for (long base = (long)gw * RB; base < n; base += stride) {
        __syncwarp();

        int rows[RB];
        #pragma unroll
        for (int r = 0; r < RB; r++) {
            long rr = base + r;
            rows[r] = (rr < n) ? (int)rr : (n - 1);
        }

        // ---- load x|v into A ----
        #pragma unroll
        for (int r = 0; r < RB; r++)
            ((float4*)slot[r])[l] = ((const float4*)(input + (size_t)rows[r] * TWOD))[l];
        __syncwarp();

        // ==== fwd1: h = tanh(W1 @ x + b1), lane owns j = l+32p — packed over k ====
        {
            ull a2[RB][4];
            #pragma unroll
            for (int r = 0; r < RB; r++)
                #pragma unroll
                for (int p = 0; p < 4; p++) a2[r][p] = pack2(b1s[l + 32 * p], 0.0f);

            const float* p0 = W1s + (l)      * W1S;
            const float* p1 = W1s + (l + 32) * W1S;
            const float* p2 = W1s + (l + 64) * W1S;
            const float* p3 = W1s + (l + 96) * W1S;
            #pragma unroll 4
            for (int k = 0; k < D; k += 4) {
                ulonglong2 q0 = *(const ulonglong2*)(p0 + k);
                ulonglong2 q1 = *(const ulonglong2*)(p1 + k);
                ulonglong2 q2 = *(const ulonglong2*)(p2 + k);
                ulonglong2 q3 = *(const ulonglong2*)(p3 + k);
                #pragma unroll
                for (int r = 0; r < RB; r++) {
                    ulonglong2 xk = *(const ulonglong2*)(slot[r] + k);   // broadcast
                    a2[r][0] = ffma2(q0.x, xk.x, a2[r][0]); a2[r][0] = ffma2(q0.y, xk.y, a2[r][0]);
                    a2[r][1] = ffma2(q1.x, xk.x, a2[r][1]); a2[r][1] = ffma2(q1.y, xk.y, a2[r][1]);
                    a2[r][2] = ffma2(q2.x, xk.x, a2[r][2]); a2[r][2] = ffma2(q2.y, xk.y, a2[r][2]);
                    a2[r][3] = ffma2(q3.x, xk.x, a2[r][3]); a2[r][3] = ffma2(q3.y, xk.y, a2[r][3]);
                }
            }
            #pragma unroll
            for (int r = 0; r < RB; r++) {
                slot[r][128 + l]      = my_tanh(hadd2(a2[r][0]));
                slot[r][128 + l + 32] = my_tanh(hadd2(a2[r][1]));
                slot[r][128 + l + 64] = my_tanh(hadd2(a2[r][2]));
                slot[r][128 + l + 96] = my_tanh(hadd2(a2[r][3]));
            }
        }
        __syncwarp();

        // ==== fwd2: m = W2 @ h + b2, lane owns j = l+32t — packed over k ====
        ull mac2[8][RB];
        #pragma unroll
        for (int t = 0; t < 8; t++)
            #pragma unroll
            for (int r = 0; r < RB; r++) mac2[t][r] = pack2(b2s[l + 32 * t], 0.0f);

        #pragma unroll 2
        for (int k4 = 0; k4 < 32; k4++) {
            const int koff = 4 * (k4 ^ l);
            ulonglong2 hk2[RB];
            #pragma unroll
            for (int r = 0; r < RB; r++) hk2[r] = *(const ulonglong2*)(slot[r] + 128 + 4 * k4);
            #pragma unroll
            for (int t = 0; t < 8; t++) {
                ulonglong2 q = *(const ulonglong2*)(W2s + (l + 32 * t) * TWOD + koff);
                #pragma unroll
                for (int r = 0; r < RB; r++) {
                    mac2[t][r] = ffma2(q.x, hk2[r].x, mac2[t][r]);
                    mac2[t][r] = ffma2(q.y, hk2[r].y, mac2[t][r]);
                }
            }
        }

        // ==== middle: wm (regs), y, dv, g — per row ====
        #pragma unroll
        for (int r = 0; r < RB; r++) {
            float wm[8], vi[8];
            #pragma unroll
            for (int t = 0; t < 8; t++) wm[t] = my_tanh(hadd2(mac2[t][r]));
            #pragma unroll
            for (int t = 0; t < 8; t++) vi[t] = slot[r][64 + (l >> 2) + 8 * t];

            float y = 0.f;
            #pragma unroll
            for (int t = 0; t < 8; t++) y = fmaf(vi[t], wm[t], y);
            y += __shfl_xor_sync(0xffffffffu, y, 4);
            y += __shfl_xor_sync(0xffffffffu, y, 8);
            y += __shfl_xor_sync(0xffffffffu, y, 16);   // y = y[l&3] on all lanes

            float* outrow = out + (size_t)rows[r] * TWOD;
            #pragma unroll
            for (int t = 0; t < 8; t++) {
                float p = y * wm[t];
                p += __shfl_xor_sync(0xffffffffu, p, 1);
                p += __shfl_xor_sync(0xffffffffu, p, 2);
                if ((l & 3) == 0) outrow[D + (l >> 2) + 8 * t] = -2.0f * p;
                float g = 2.0f * y * vi[t] * (1.0f - wm[t] * wm[t]);
                if (t < 4) slot[r][l + 32 * t]             = g;   // g_lo over dead x|v
                else       slot[r][256 + l + 32 * t - 128] = g;   // g_hi in C
            }
        }
        __syncwarp();

        // ==== bwd W2: dh[k] = sum_j W2[j][k]*g[j]; lane owns k = 4l..4l+3 — packed over k ====
        {
            ull dacc2[RB][2];
            #pragma unroll
            for (int r = 0; r < RB; r++) { dacc2[r][0] = 0ull; dacc2[r][1] = 0ull; }

            #pragma unroll 2
            for (int jq = 0; jq < 64; jq++) {
                const int j  = 4 * jq;
                const int jb = j & 31;
                const float* wp = W2s + j * TWOD;
                ulonglong2 q0 = *(const ulonglong2*)(wp            + 4 * (l ^ (jb)));
                ulonglong2 q1 = *(const ulonglong2*)(wp + TWOD     + 4 * (l ^ (jb + 1)));
                ulonglong2 q2 = *(const ulonglong2*)(wp + 2 * TWOD + 4 * (l ^ (jb + 2)));
                ulonglong2 q3 = *(const ulonglong2*)(wp + 3 * TWOD + 4 * (l ^ (jb + 3)));
                const int goff = (jq < 32) ? j : (256 + j - 128);
                #pragma unroll
                for (int r = 0; r < RB; r++) {
                    float4 gq = *(const float4*)(slot[r] + goff);    // broadcast
                    ull gx = pack2(gq.x, gq.x), gy = pack2(gq.y, gq.y);
                    ull gz = pack2(gq.z, gq.z), gw = pack2(gq.w, gq.w);
                    dacc2[r][0] = ffma2(gx, q0.x, dacc2[r][0]);
                    dacc2[r][0] = ffma2(gy, q1.x, dacc2[r][0]);
                    dacc2[r][0] = ffma2(gz, q2.x, dacc2[r][0]);
                    dacc2[r][0] = ffma2(gw, q3.x, dacc2[r][0]);
                    dacc2[r][1] = ffma2(gx, q0.y, dacc2[r][1]);
                    dacc2[r][1] = ffma2(gy, q1.y, dacc2[r][1]);
                    dacc2[r][1] = ffma2(gz, q2.y, dacc2[r][1]);
                    dacc2[r][1] = ffma2(gw, q3.y, dacc2[r][1]);
                }
            }
            __syncwarp();   // all g reads done before du overwrites A
            #pragma unroll
            for (int r = 0; r < RB; r++) {
                float2 dA = unpack2(dacc2[r][0]);
                float2 dB = unpack2(dacc2[r][1]);
                float4 hk = *(const float4*)(slot[r] + 128 + 4 * l);
                float4 du;
                du.x = dA.x * (1.0f - hk.x * hk.x);
                du.y = dA.y * (1.0f - hk.y * hk.y);
                du.z = dB.x * (1.0f - hk.z * hk.z);
                du.w = dB.y * (1.0f - hk.w * hk.w);
                *(float4*)(slot[r] + 4 * l) = du;     // du over g_lo
            }
        }
        __syncwarp();

        // ==== bwd W1: dx[i] = sum_j W1[j][i]*du[j]; lane owns i = 2l,2l+1 — packed over i ====
        {
            ull xo2[RB];
            #pragma unroll
            for (int r = 0; r < RB; r++) xo2[r] = 0ull;
            const float* c1 = W1s + 2 * l;
            #pragma unroll 2
            for (int jq = 0; jq < 32; jq++) {
                const int j = 4 * jq;
                ull c0 = *(const ull*)(c1 + (j)     * W1S);
                ull ca = *(const ull*)(c1 + (j + 1) * W1S);
                ull cb = *(const ull*)(c1 + (j + 2) * W1S);
                ull cc = *(const ull*)(c1 + (j + 3) * W1S);
                #pragma unroll
                for (int r = 0; r < RB; r++) {
                    float4 dq = *(const float4*)(slot[r] + j);   // du broadcast
                    xo2[r] = ffma2(pack2(dq.x, dq.x), c0, xo2[r]);
                    xo2[r] = ffma2(pack2(dq.y, dq.y), ca, xo2[r]);
                    xo2[r] = ffma2(pack2(dq.z, dq.z), cb, xo2[r]);
                    xo2[r] = ffma2(pack2(dq.w, dq.w), cc, xo2[r]);
                }
            }
            #pragma unroll
            for (int r = 0; r < RB; r++) {
                float2 xr = unpack2(xo2[r]);
                *(float2*)(out + (size_t)rows[r] * TWOD + 2 * l) = xr;
            }
        }
    }
}

extern "C" void kernel_launch(void* const* d_in, const int* in_sizes, int n_in,
                              void* d_out, int out_size) {
    // inputs: t(1), input_(N*128), W1(128*64), b1(128), W2(256*128), b2(256)
    const float* input = (const float*)d_in[1];
    const float* W1    = (const float*)d_in[2];
    const float* b1    = (const float*)d_in[3];
    const float* W2    = (const float*)d_in[4];
    const float* b2    = (const float*)d_in[5];
    float* out = (float*)d_out;
    const int n = in_sizes[1] / TWOD;

    static_assert(SMEM_FLOATS * 4 < 232448, "smem budget");

    int dev = 0;
    cudaGetDevice(&dev);
    int nsm = 148;
    cudaDeviceGetAttribute(&nsm, cudaDevAttrMultiProcessorCount, dev);

    cudaFuncSetAttribute(geognn_grad_kernel,
                         cudaFuncAttributeMaxDynamicSharedMemorySize,
                         SMEM_FLOATS * (int)sizeof(float));

    geognn_grad_kernel<<<nsm, THREADS, SMEM_FLOATS * (int)sizeof(float)>>>(
        input, W1, b1, W2, b2, out, n);
}

// round 14
// speedup vs baseline: 1.2838x; 1.0028x over previous
#include <cuda_runtime.h>
#include <math.h>

#define D 64
#define TWOD 128
#define RD 256            // RANK*D
#define W1S 68            // padded stride for W1 rows (conflict-free LDS.128 both ways)
#define WARPS 8
#define THREADS 256
#define RB 5              // rows per warp
#define SLOT 384          // per-row scratch: A[128]=x|v->g_lo->du, B[128]=h, C[128]=g_hi

// W2 stored stride-128 with XOR chunk swizzle
#define SMEM_FLOATS (TWOD*W1S + RD*TWOD + TWOD + RD + WARPS*RB*SLOT)

typedef unsigned long long ull;

__device__ __forceinline__ ull pack2(float lo, float hi) {
    ull r; asm("mov.b64 %0, {%1, %2};" : "=l"(r) : "f"(lo), "f"(hi)); return r;
}
__device__ __forceinline__ float2 unpack2(ull v) {
    float2 f; asm("mov.b64 {%0, %1}, %2;" : "=f"(f.x), "=f"(f.y) : "l"(v)); return f;
}
__device__ __forceinline__ ull ffma2(ull a, ull b, ull c) {
    ull d; asm("fma.rn.f32x2 %0, %1, %2, %3;" : "=l"(d) : "l"(a), "l"(b), "l"(c)); return d;
}
__device__ __forceinline__ float hadd2(ull v) { float2 f = unpack2(v); return f.x + f.y; }

__device__ __forceinline__ float my_tanh(float x) {
    float xc = fminf(fmaxf(x, -10.0f), 10.0f);
    float e = __expf(2.0f * xc);
    return __fdividef(e - 1.0f, e + 1.0f);
}

__global__ __launch_bounds__(THREADS, 1)
void geognn_grad_kernel(const float* __restrict__ input,
                        const float* __restrict__ W1, const float* __restrict__ b1,
                        const float* __restrict__ W2, const float* __restrict__ b2,
                        float* __restrict__ out, int n)
{
    extern __shared__ float smem[];
    float* W1s = smem;                 // [128][68]
    float* W2s = W1s + TWOD * W1S;     // [256][128], chunk k4 stored at k4^(j&31)
    float* b1s = W2s + RD * TWOD;      // [128]
    float* b2s = b1s + TWOD;           // [256]
    float* scr = b2s + RD;

    const int tid = threadIdx.x;
    const int w   = tid >> 5;
    const int l   = tid & 31;

    // ---- cooperative weight staging ----
    {
        const float4* W1v = (const float4*)W1;
        for (int i = tid; i < TWOD * (D / 4); i += THREADS) {
            int j = i >> 4, k4 = i & 15;
            *(float4*)(W1s + j * W1S + 4 * k4) = W1v[i];
        }
        const float4* W2v = (const float4*)W2;
        for (int i = tid; i < RD * (TWOD / 4); i += THREADS) {
            int j = i >> 5, k4 = i & 31;
            *(float4*)(W2s + j * TWOD + 4 * (k4 ^ (j & 31))) = W2v[i];
        }
        for (int i = tid; i < TWOD; i += THREADS) b1s[i] = b1[i];
        for (int i = tid; i < RD;   i += THREADS) b2s[i] = b2[i];
    }
    __syncthreads();

    float* slot[RB];
    #pragma unroll
    for (int r = 0; r < RB; r++) slot[r] = scr + (w * RB + r) * SLOT;

    const int gw = blockIdx.x * WARPS + w;
    const long stride = (long)gridDim.x * WARPS * RB;

    for (long base = (long)gw * RB; base < n; base += stride) {
        __syncwarp();

        int rows[RB];
        #pragma unroll
        for (int r = 0; r < RB; r++) {
            long rr = base + r;
            rows[r] = (rr < n) ? (int)rr : (n - 1);
        }

        // ---- load x|v into A ----
        #pragma unroll
        for (int r = 0; r < RB; r++)
            ((float4*)slot[r])[l] = ((const float4*)(input + (size_t)rows[r] * TWOD))[l];
        __syncwarp();

        // ==== fwd1: h = tanh(W1 @ x + b1), lane owns j = l+32p — packed over k ====
        {
            ull a2[RB][4];
            #pragma unroll
            for (int r = 0; r < RB; r++)
                #pragma unroll
                for (int p = 0; p < 4; p++) a2[r][p] = pack2(b1s[l + 32 * p], 0.0f);

            const float* p0 = W1s + (l)      * W1S;
            const float* p1 = W1s + (l + 32) * W1S;
            const float* p2 = W1s + (l + 64) * W1S;
            const float* p3 = W1s + (l + 96) * W1S;
            #pragma unroll 4
            for (int k = 0; k < D; k += 4) {
                ulonglong2 q0 = *(const ulonglong2*)(p0 + k);
                ulonglong2 q1 = *(const ulonglong2*)(p1 + k);
                ulonglong2 q2 = *(const ulonglong2*)(p2 + k);
                ulonglong2 q3 = *(const ulonglong2*)(p3 + k);
                #pragma unroll
                for (int r = 0; r < RB; r++) {
                    ulonglong2 xk = *(const ulonglong2*)(slot[r] + k);   // broadcast
                    a2[r][0] = ffma2(q0.x, xk.x, a2[r][0]); a2[r][0] = ffma2(q0.y, xk.y, a2[r][0]);
                    a2[r][1] = ffma2(q1.x, xk.x, a2[r][1]); a2[r][1] = ffma2(q1.y, xk.y, a2[r][1]);
                    a2[r][2] = ffma2(q2.x, xk.x, a2[r][2]); a2[r][2] = ffma2(q2.y, xk.y, a2[r][2]);
                    a2[r][3] = ffma2(q3.x, xk.x, a2[r][3]); a2[r][3] = ffma2(q3.y, xk.y, a2[r][3]);
                }
            }
            #pragma unroll
            for (int r = 0; r < RB; r++) {
                slot[r][128 + l]      = my_tanh(hadd2(a2[r][0]));
                slot[r][128 + l + 32] = my_tanh(hadd2(a2[r][1]));
                slot[r][128 + l + 64] = my_tanh(hadd2(a2[r][2]));
                slot[r][128 + l + 96] = my_tanh(hadd2(a2[r][3]));
            }
        }
        __syncwarp();

        // ==== fwd2: m = W2 @ h + b2, lane owns j = l+32t — packed over k ====
        ull mac2[8][RB];
        #pragma unroll
        for (int t = 0; t < 8; t++)
            #pragma unroll
            for (int r = 0; r < RB; r++) mac2[t][r] = pack2(b2s[l + 32 * t], 0.0f);

        #pragma unroll 2
        for (int k4 = 0; k4 < 32; k4++) {
            const int koff = 4 * (k4 ^ l);
            ulonglong2 hk2[RB];
            #pragma unroll
            for (int r = 0; r < RB; r++) hk2[r] = *(const ulonglong2*)(slot[r] + 128 + 4 * k4);
            #pragma unroll
            for (int t = 0; t < 8; t++) {
                ulonglong2 q = *(const ulonglong2*)(W2s + (l + 32 * t) * TWOD + koff);
                #pragma unroll
                for (int r = 0; r < RB; r++) {
                    mac2[t][r] = ffma2(q.x, hk2[r].x, mac2[t][r]);
                    mac2[t][r] = ffma2(q.y, hk2[r].y, mac2[t][r]);
                }
            }
        }

        // ==== middle: wm (regs), y, dv, g — per row ====
        #pragma unroll
        for (int r = 0; r < RB; r++) {
            float wm[8], vi[8];
            #pragma unroll
            for (int t = 0; t < 8; t++) wm[t] = my_tanh(hadd2(mac2[t][r]));
            #pragma unroll
            for (int t = 0; t < 8; t++) vi[t] = slot[r][64 + (l >> 2) + 8 * t];

            float y = 0.f;
            #pragma unroll
            for (int t = 0; t < 8; t++) y = fmaf(vi[t], wm[t], y);
            y += __shfl_xor_sync(0xffffffffu, y, 4);
            y += __shfl_xor_sync(0xffffffffu, y, 8);
            y += __shfl_xor_sync(0xffffffffu, y, 16);   // y = y[l&3] on all lanes

            float* outrow = out + (size_t)rows[r] * TWOD;
            #pragma unroll
            for (int t = 0; t < 8; t++) {
                float p = y * wm[t];
                p += __shfl_xor_sync(0xffffffffu, p, 1);
                p += __shfl_xor_sync(0xffffffffu, p, 2);
                if ((l & 3) == 0) outrow[D + (l >> 2) + 8 * t] = -2.0f * p;
                float g = 2.0f * y * vi[t] * (1.0f - wm[t] * wm[t]);
                if (t < 4) slot[r][l + 32 * t]             = g;   // g_lo over dead x|v
                else       slot[r][256 + l + 32 * t - 128] = g;   // g_hi in C
            }
        }
        __syncwarp();

        // ==== bwd W2: dh[k] = sum_j W2[j][k]*g[j]; lane owns k = 4l..4l+3 — packed over k ====
        {
            ull dacc2[RB][2];
            #pragma unroll
            for (int r = 0; r < RB; r++) { dacc2[r][0] = 0ull; dacc2[r][1] = 0ull; }

            #pragma unroll 2
            for (int jq = 0; jq < 64; jq++) {
                const int j  = 4 * jq;
                const int jb = j & 31;
                const float* wp = W2s + j * TWOD;
                ulonglong2 q0 = *(const ulonglong2*)(wp            + 4 * (l ^ (jb)));
                ulonglong2 q1 = *(const ulonglong2*)(wp + TWOD     + 4 * (l ^ (jb + 1)));
                ulonglong2 q2 = *(const ulonglong2*)(wp + 2 * TWOD + 4 * (l ^ (jb + 2)));
                ulonglong2 q3 = *(const ulonglong2*)(wp + 3 * TWOD + 4 * (l ^ (jb + 3)));
                const int goff = (jq < 32) ? j : (256 + j - 128);
                #pragma unroll
                for (int r = 0; r < RB; r++) {
                    float4 gq = *(const float4*)(slot[r] + goff);    // broadcast
                    ull gx = pack2(gq.x, gq.x), gy = pack2(gq.y, gq.y);
                    ull gz = pack2(gq.z, gq.z), gw = pack2(gq.w, gq.w);
                    dacc2[r][0] = ffma2(gx, q0.x, dacc2[r][0]);
                    dacc2[r][0] = ffma2(gy, q1.x, dacc2[r][0]);
                    dacc2[r][0] = ffma2(gz, q2.x, dacc2[r][0]);
                    dacc2[r][0] = ffma2(gw, q3.x, dacc2[r][0]);
                    dacc2[r][1] = ffma2(gx, q0.y, dacc2[r][1]);
                    dacc2[r][1] = ffma2(gy, q1.y, dacc2[r][1]);
                    dacc2[r][1] = ffma2(gz, q2.y, dacc2[r][1]);
                    dacc2[r][1] = ffma2(gw, q3.y, dacc2[r][1]);
                }
            }
            __syncwarp();   // all g reads done before du overwrites A
            #pragma unroll
            for (int r = 0; r < RB; r++) {
                float2 dA = unpack2(dacc2[r][0]);
                float2 dB = unpack2(dacc2[r][1]);
                float4 hk = *(const float4*)(slot[r] + 128 + 4 * l);
                float4 du;
                du.x = dA.x * (1.0f - hk.x * hk.x);
                du.y = dA.y * (1.0f - hk.y * hk.y);
                du.z = dB.x * (1.0f - hk.z * hk.z);
                du.w = dB.y * (1.0f - hk.w * hk.w);
                *(float4*)(slot[r] + 4 * l) = du;     // du over g_lo
            }
        }
        __syncwarp();

        // ==== bwd W1: dx[i] = sum_j W1[j][i]*du[j]; lane owns i = 2l,2l+1 — packed over i ====
        {
            ull xo2[RB];
            #pragma unroll
            for (int r = 0; r < RB; r++) xo2[r] = 0ull;
            const float* c1 = W1s + 2 * l;
            #pragma unroll 2
            for (int jq = 0; jq < 32; jq++) {
                const int j = 4 * jq;
                ull c0 = *(const ull*)(c1 + (j)     * W1S);
                ull ca = *(const ull*)(c1 + (j + 1) * W1S);
                ull cb = *(const ull*)(c1 + (j + 2) * W1S);
                ull cc = *(const ull*)(c1 + (j + 3) * W1S);
                #pragma unroll
                for (int r = 0; r < RB; r++) {
                    float4 dq = *(const float4*)(slot[r] + j);   // du broadcast
                    xo2[r] = ffma2(pack2(dq.x, dq.x), c0, xo2[r]);
                    xo2[r] = ffma2(pack2(dq.y, dq.y), ca, xo2[r]);
                    xo2[r] = ffma2(pack2(dq.z, dq.z), cb, xo2[r]);
                    xo2[r] = ffma2(pack2(dq.w, dq.w), cc, xo2[r]);
                }
            }
            #pragma unroll
            for (int r = 0; r < RB; r++) {
                float2 xr = unpack2(xo2[r]);
                *(float2*)(out + (size_t)rows[r] * TWOD + 2 * l) = xr;
            }
        }
    }
}

extern "C" void kernel_launch(void* const* d_in, const int* in_sizes, int n_in,
                              void* d_out, int out_size) {
    // inputs: t(1), input_(N*128), W1(128*64), b1(128), W2(256*128), b2(256)
    const float* input = (const float*)d_in[1];
    const float* W1    = (const float*)d_in[2];
    const float* b1    = (const float*)d_in[3];
    const float* W2    = (const float*)d_in[4];
    const float* b2    = (const float*)d_in[5];
    float* out = (float*)d_out;
    const int n = in_sizes[1] / TWOD;

    static_assert(SMEM_FLOATS * 4 < 232448, "smem budget");

    int dev = 0;
    cudaGetDevice(&dev);
    int nsm = 148;
    cudaDeviceGetAttribute(&nsm, cudaDevAttrMultiProcessorCount, dev);

    cudaFuncSetAttribute(geognn_grad_kernel,
                         cudaFuncAttributeMaxDynamicSharedMemorySize,
                         SMEM_FLOATS * (int)sizeof(float));

    geognn_grad_kernel<<<nsm, THREADS, SMEM_FLOATS * (int)sizeof(float)>>>(
        input, W1, b1, W2, b2, out, n);
}